// round 12
// baseline (speedup 1.0000x reference)
#include <cuda_runtime.h>
#include <cuda_bf16.h>
#include <stdint.h>

#define KTOT 1024
#define DIM  64
#define HW   4096
#define QELEMS 4194304
#define DELTA 2.5e-3f
#define INF __int_as_float(0x7f800000)

// dynamic smem offsets (bytes)
#define XS_OFF 0        // f32 xs[64][64]               16384
#define B_OFF  16384    // bf16 B[256][72] padded       36864
#define CN_OFF 53248    // f32 cn[256]                   1024
#define GM_OFF 54272    // f32 gmin[64][33] padded       8448
#define XN_OFF 62720    // f32 xn[64]                     256
#define TR_OFF 62976    // f32 thr[64]                    256
#define BM_OFF 63232    // u64 brm[64]                    512
#define WL_OFF 63744    // u16 wl[2048]                  4096
#define WC_OFF 67840    // i32 wcnt                        16
#define SI_OFF 67856    // i32 sid[64]                    256
#define LR_OFF 68112    // f32 lred[256]                 1024
#define SMEM_BYTES 69152

__device__ float g_cnorm[KTOT];
__device__ __align__(16) __nv_bfloat16 g_cbb[KTOT*DIM];

__global__ void vq_prep(const float* __restrict__ cb, float* __restrict__ loss_ptr){
    int k = blockIdx.x*256 + threadIdx.x;
    if (k==0) *loss_ptr = 0.0f;
    if (k < KTOT){
        float s = 0.0f;
        #pragma unroll
        for (int d=0; d<DIM; ++d){
            float c = cb[k*DIM+d];
            g_cbb[k*DIM+d] = __float2bfloat16(c);
            s = __fadd_rn(s, __fmul_rn(c,c));
        }
        g_cnorm[k] = s;
    }
}

__device__ __forceinline__ uint32_t packbf(float lo, float hi){
    __nv_bfloat162 h = __floats2bfloat162_rn(lo, hi);
    return *(uint32_t*)&h;
}
__device__ __forceinline__ uint32_t f2o(float f){
    uint32_t u = __float_as_uint(f);
    return (u & 0x80000000u) ? ~u : (u | 0x80000000u);
}
__device__ __forceinline__ uint32_t s2u(const void* p){
    uint32_t a; asm("{ .reg .u64 t; cvta.to.shared.u64 t, %1; cvt.u32.u64 %0, t; }":"=r"(a):"l"(p)); return a;
}
#define HMMA(acc,a,b0,b1) asm volatile( \
    "mma.sync.aligned.m16n8k16.row.col.f32.bf16.bf16.f32 " \
    "{%0,%1,%2,%3}, {%4,%5,%6,%7}, {%8,%9}, {%0,%1,%2,%3};" \
    : "+f"((acc)[0]),"+f"((acc)[1]),"+f"((acc)[2]),"+f"((acc)[3]) \
    : "r"((a)[0]),"r"((a)[1]),"r"((a)[2]),"r"((a)[3]), "r"(b0),"r"(b1))
#define LDSM4(r,a) asm volatile( \
    "ldmatrix.sync.aligned.m8n8.x4.shared.b16 {%0,%1,%2,%3}, [%4];" \
    : "=r"((r)[0]),"=r"((r)[1]),"=r"((r)[2]),"=r"((r)[3]) : "r"(a))
#define CPASYNC16(dst,src) asm volatile( \
    "cp.async.cg.shared.global [%0], [%1], 16;" :: "r"(dst), "l"(src))

// exact R1-numerics score for row rw (smem xs [d][64]) vs codebook row k
__device__ __forceinline__ float exact_score(const float* xs, const float* cb,
                                             int rw, int k, float xnv){
    const float4* cr = (const float4*)(cb + k*DIM);
    float dot = 0.0f;
    #pragma unroll
    for (int q=0; q<16; ++q){
        float4 c = __ldg(cr+q);
        int d0 = q*4;
        dot = fmaf(xs[d0*64+rw],     c.x, dot);
        dot = fmaf(xs[(d0+1)*64+rw], c.y, dot);
        dot = fmaf(xs[(d0+2)*64+rw], c.z, dot);
        dot = fmaf(xs[(d0+3)*64+rw], c.w, dot);
    }
    return __fsub_rn(__fadd_rn(xnv, __ldg(&g_cnorm[k])), __fmul_rn(2.0f, dot));
}

__global__ void __launch_bounds__(256,3) vq_hmma_kernel(
    const float* __restrict__ x, const float* __restrict__ cb,
    float* __restrict__ out, float* __restrict__ loss_ptr)
{
    extern __shared__ char smc[];
    float*              xs  = (float*)(smc + XS_OFF);
    float*              cns = (float*)(smc + CN_OFF);
    float*              gmS = (float*)(smc + GM_OFF);
    float*              xns = (float*)(smc + XN_OFF);
    float*              thrS= (float*)(smc + TR_OFF);
    unsigned long long* brm = (unsigned long long*)(smc + BM_OFF);
    uint16_t*           wl  = (uint16_t*)(smc + WL_OFF);
    int*                wc  = (int*)(smc + WC_OFF);
    int*                sid = (int*)(smc + SI_OFF);
    float*              lrd = (float*)(smc + LR_OFF);
    const uint32_t Bu  = s2u(smc + B_OFF);
    const uint32_t CNu = s2u(smc + CN_OFF);

    const int tid = threadIdx.x;
    const int b = blockIdx.x>>6, h = blockIdx.x&63;

    if (tid==0) wc[0] = 0;
    if (tid<64) brm[tid] = ~0ull;

    // ---- load x tile [64d][64w] (coalesced over w) ----
    {
        int w2 = tid&63, d0 = tid>>6;
        const float* xb = x + (size_t)b*DIM*HW + (size_t)h*64 + w2;
        #pragma unroll
        for (int i=0;i<16;i++){ int d = d0*16+i; xs[d*64+w2] = xb[(size_t)d*HW]; }
    }
    __syncthreads();

    // ---- per-row ||x||^2 (mul/add, ascending d) ----
    if (tid<64){
        float s=0.0f;
        #pragma unroll
        for (int d=0; d<DIM; ++d){ float v=xs[d*64+tid]; s=__fadd_rn(s,__fmul_rn(v,v)); }
        xns[tid]=s;
    }

    const int lane = tid&31, w = tid>>5;
    const int g = lane>>2, tg = lane&3;
    const int mbase = (w&3)*16, nh = w>>2;   // 4 m-quarters x 2 n-halves
    const int R0 = mbase+g, R1 = R0+8;
    const uint32_t lds_base = Bu + (uint32_t)(lane&7)*144u + (uint32_t)(lane>>3)*16u;

    // ---- A fragments (one m16 tile per warp, m16n8k16 row-major) ----
    uint32_t afr[4][4];
    #pragma unroll
    for (int ks=0; ks<4; ++ks){
        int c0 = ks*16 + 2*tg, c2 = c0 + 8;
        afr[ks][0] = packbf(xs[c0*64+R0], xs[(c0+1)*64+R0]);
        afr[ks][1] = packbf(xs[c0*64+R1], xs[(c0+1)*64+R1]);
        afr[ks][2] = packbf(xs[c2*64+R0], xs[(c2+1)*64+R0]);
        afr[ks][3] = packbf(xs[c2*64+R1], xs[(c2+1)*64+R1]);
    }

    // ================= single HMMA pass: per-(row, 32k-group) min =================
    #pragma unroll 1
    for (int ch=0; ch<4; ++ch){
        // ---- stage B chunk via cp.async (256k x 128B) + cn ----
        {
            const uint4* src = ((const uint4*)g_cbb) + ch*2048;
            #pragma unroll
            for (int j=tid; j<2048; j+=256){
                uint32_t dst = Bu + (uint32_t)(j>>3)*144u + (uint32_t)(j&7)*16u;
                CPASYNC16(dst, src + j);
            }
            if (tid<64)
                CPASYNC16(CNu + tid*16u, (const uint4*)(g_cnorm + ch*256) + tid);
            asm volatile("cp.async.commit_group;" ::: "memory");
            asm volatile("cp.async.wait_group 0;" ::: "memory");
        }
        __syncthreads();

        #pragma unroll 1
        for (int it=0; it<4; ++it){
            int n0 = nh*128 + it*32;                  // 4 n8 tiles
            float acc[4][4];
            #pragma unroll
            for (int t=0;t<4;++t){ acc[t][0]=0;acc[t][1]=0;acc[t][2]=0;acc[t][3]=0; }

            #pragma unroll
            for (int pr=0; pr<2; ++pr){
                int t0 = pr*2, t1 = t0+1;
                uint32_t f0[8], f1[8];
                uint32_t a0 = lds_base + (uint32_t)(n0 + 8*t0)*144u;
                uint32_t a1 = lds_base + (uint32_t)(n0 + 8*t1)*144u;
                LDSM4(f0,   a0); LDSM4(f0+4, a0+64u);
                LDSM4(f1,   a1); LDSM4(f1+4, a1+64u);
                #pragma unroll
                for (int ks=0; ks<4; ++ks){
                    HMMA(acc[t0], afr[ks], f0[2*ks], f0[2*ks+1]);
                    HMMA(acc[t1], afr[ks], f1[2*ks], f1[2*ks+1]);
                }
            }

            float s[16];
            #pragma unroll
            for (int t=0;t<4;++t){
                float2 cn2 = *(const float2*)&cns[n0 + 8*t + 2*tg];
                s[t*4+0] = fmaf(-2.0f, acc[t][0], cn2.x);
                s[t*4+1] = fmaf(-2.0f, acc[t][1], cn2.y);
                s[t*4+2] = fmaf(-2.0f, acc[t][2], cn2.x);
                s[t*4+3] = fmaf(-2.0f, acc[t][3], cn2.y);
            }
            float im0 = fminf(fminf(s[0],s[1]),  fminf(s[4],s[5]));
            im0 = fminf(im0, fminf(fminf(s[8],s[9]),  fminf(s[12],s[13])));
            float im1 = fminf(fminf(s[2],s[3]),  fminf(s[6],s[7]));
            im1 = fminf(im1, fminf(fminf(s[10],s[11]),fminf(s[14],s[15])));
            // quad reduce over tg (lanes g*4+tg share rows R0/R1) -> full 32k-group min
            im0 = fminf(im0, __shfl_xor_sync(0xffffffffu, im0, 1));
            im0 = fminf(im0, __shfl_xor_sync(0xffffffffu, im0, 2));
            im1 = fminf(im1, __shfl_xor_sync(0xffffffffu, im1, 1));
            im1 = fminf(im1, __shfl_xor_sync(0xffffffffu, im1, 2));
            if (tg==0){
                int gidx = ch*8 + nh*4 + it;
                gmS[R0*33 + gidx] = im0;
                gmS[R1*33 + gidx] = im1;
            }
        }
        __syncthreads();   // B + gmin of this chunk consumed/ordered
    }

    // ================= threshold + compacted worklist =================
    if (tid < 64){
        float m = INF;
        #pragma unroll
        for (int g2=0; g2<32; ++g2) m = fminf(m, gmS[tid*33+g2]);
        float thrv = m + DELTA;
        thrS[tid] = thrv;
        for (int g2=0; g2<32; ++g2)
            if (gmS[tid*33+g2] < thrv){
                int pos = atomicAdd(wc, 1);      // capacity 2048 == theoretical max
                wl[pos] = (uint16_t)(tid*32 + g2);
            }
    }
    __syncthreads();

    // ================= uniform exact rescore (R1 numerics) =================
    {
        int nw = wc[0];
        int sl = tid&3;
        for (int i = tid>>2; i < nw; i += 64){
            int item = wl[i];
            int row = item>>5, g2 = item&31;
            float xnv = xns[row];
            int kb = g2*32 + sl*8;
            unsigned long long bl = ~0ull;
            #pragma unroll
            for (int j=0;j<8;++j){
                int k = kb + j;
                float sc = exact_score(xs, cb, row, k, xnv);
                unsigned long long p = ((unsigned long long)f2o(sc)<<32) | (unsigned)k;
                if (p < bl) bl = p;
            }
            atomicMin(&brm[row], bl);
        }
    }
    __syncthreads();
    if (tid<64) sid[tid] = (int)(brm[tid] & 0x3FFull);
    __syncthreads();

    // ---- straight-through output + loss (R1 elementwise rounding) ----
    float lsum = 0.0f;
    {
        int w2 = tid&63, d0 = tid>>6;
        int k = sid[w2];
        const float* cr = cb + k*DIM;
        float* ob = out + (size_t)b*DIM*HW + (size_t)h*64 + w2;
        #pragma unroll
        for (int i=0;i<16;i++){
            int d = d0*16+i;
            float q = __ldg(cr+d), xv = xs[d*64+w2];
            float df = __fsub_rn(q, xv);
            lsum = __fadd_rn(lsum, __fmul_rn(df, df));
            ob[(size_t)d*HW] = __fadd_rn(xv, df);
        }
    }
    lrd[tid] = lsum;
    __syncthreads();
    #pragma unroll
    for (int s2=128; s2>0; s2>>=1){
        if (tid<s2) lrd[tid] = __fadd_rn(lrd[tid], lrd[tid+s2]);
        __syncthreads();
    }
    if (tid==0) atomicAdd(loss_ptr, lrd[0] * (1.25f/(float)QELEMS));
}

extern "C" void kernel_launch(void* const* d_in, const int* in_sizes, int n_in,
                              void* d_out, int out_size) {
    const float* x  = (const float*)d_in[0];
    const float* cb = (const float*)d_in[1];
    float* out = (float*)d_out;
    float* loss_ptr = out + (out_size - 1);

    cudaFuncSetAttribute(vq_hmma_kernel, cudaFuncAttributeMaxDynamicSharedMemorySize, SMEM_BYTES);
    vq_prep<<<4, 256>>>(cb, loss_ptr);
    vq_hmma_kernel<<<1024, 256, SMEM_BYTES>>>(x, cb, out, loss_ptr);
}

// round 14
// speedup vs baseline: 1.2827x; 1.2827x over previous
#include <cuda_runtime.h>
#include <cuda_bf16.h>
#include <stdint.h>

#define KTOT 1024
#define DIM  64
#define HW   4096
#define QELEMS 4194304
#define DELTA 2.5e-3f
#define INF __int_as_float(0x7f800000)

// dynamic smem offsets (bytes); B stride = 144 bytes/row (16B-aligned!)
#define XS_OFF 0        // f32 xs[64][64]               16384
#define B_OFF  16384    // bf16 B[256][72] (144B rows)  36864
#define CN_OFF 53248    // f32 cn[256]                   1024
#define GM_OFF 54272    // f32 gmin[64][65] padded      16640
#define XN_OFF 70912    // f32 xn[64]                     256
#define TP_OFF 71168    // f32 tp[64][4]                 1024
#define TR_OFF 72192    // f32 thr[64]                    256
#define BM_OFF 72448    // u64 brm[64]                    512
#define SI_OFF 72960    // i32 sid[64]                    256
#define LR_OFF 73216    // f32 lred[256]                 1024
#define WC_OFF 74240    // i32 wcnt                        16
#define SMEM_BYTES 74256
// wl[4096] u16 aliases the dead B buffer after pass 1 (capacity == theoretical max)

__device__ float g_cnorm[KTOT];
__device__ __align__(16) __nv_bfloat16 g_cbb[KTOT*DIM];

__global__ void vq_prep(const float* __restrict__ cb, float* __restrict__ loss_ptr){
    int k = blockIdx.x*256 + threadIdx.x;
    if (k==0) *loss_ptr = 0.0f;
    if (k < KTOT){
        float s = 0.0f;
        #pragma unroll
        for (int d=0; d<DIM; ++d){
            float c = cb[k*DIM+d];
            g_cbb[k*DIM+d] = __float2bfloat16(c);
            s = __fadd_rn(s, __fmul_rn(c,c));
        }
        g_cnorm[k] = s;
    }
}

__device__ __forceinline__ uint32_t packbf(float lo, float hi){
    __nv_bfloat162 h = __floats2bfloat162_rn(lo, hi);
    return *(uint32_t*)&h;
}
__device__ __forceinline__ uint32_t f2o(float f){
    uint32_t u = __float_as_uint(f);
    return (u & 0x80000000u) ? ~u : (u | 0x80000000u);
}
__device__ __forceinline__ uint32_t s2u(const void* p){
    uint32_t a; asm("{ .reg .u64 t; cvta.to.shared.u64 t, %1; cvt.u32.u64 %0, t; }":"=r"(a):"l"(p)); return a;
}
#define HMMA(acc,a,b0,b1) asm volatile( \
    "mma.sync.aligned.m16n8k16.row.col.f32.bf16.bf16.f32 " \
    "{%0,%1,%2,%3}, {%4,%5,%6,%7}, {%8,%9}, {%0,%1,%2,%3};" \
    : "+f"((acc)[0]),"+f"((acc)[1]),"+f"((acc)[2]),"+f"((acc)[3]) \
    : "r"((a)[0]),"r"((a)[1]),"r"((a)[2]),"r"((a)[3]), "r"(b0),"r"(b1))
#define LDSM4(r,a) asm volatile( \
    "ldmatrix.sync.aligned.m8n8.x4.shared.b16 {%0,%1,%2,%3}, [%4];" \
    : "=r"((r)[0]),"=r"((r)[1]),"=r"((r)[2]),"=r"((r)[3]) : "r"(a))
#define CPASYNC16(dst,src) asm volatile( \
    "cp.async.cg.shared.global [%0], [%1], 16;" :: "r"(dst), "l"(src))

// exact rescore of 4 consecutive k (kb..kb+3) for one row; each dot is a single
// sequential ascending-d fmaf chain (R1 numerics); loads interleaved for MLP=4.
__device__ __forceinline__ unsigned long long rescore4(
    const float* xs, const float* cb, int row, int kb, float xnv)
{
    const float4* c0 = (const float4*)(cb + (kb+0)*DIM);
    const float4* c1 = (const float4*)(cb + (kb+1)*DIM);
    const float4* c2 = (const float4*)(cb + (kb+2)*DIM);
    const float4* c3 = (const float4*)(cb + (kb+3)*DIM);
    float d0=0.f, d1=0.f, d2=0.f, d3=0.f;
    #pragma unroll
    for (int q=0; q<16; ++q){
        float4 a = __ldg(c0+q), b = __ldg(c1+q), c = __ldg(c2+q), e = __ldg(c3+q);
        int dd = q*4;
        float x0 = xs[dd*64+row], x1 = xs[(dd+1)*64+row];
        float x2 = xs[(dd+2)*64+row], x3 = xs[(dd+3)*64+row];
        d0 = fmaf(x0,a.x,d0); d0 = fmaf(x1,a.y,d0); d0 = fmaf(x2,a.z,d0); d0 = fmaf(x3,a.w,d0);
        d1 = fmaf(x0,b.x,d1); d1 = fmaf(x1,b.y,d1); d1 = fmaf(x2,b.z,d1); d1 = fmaf(x3,b.w,d1);
        d2 = fmaf(x0,c.x,d2); d2 = fmaf(x1,c.y,d2); d2 = fmaf(x2,c.z,d2); d2 = fmaf(x3,c.w,d2);
        d3 = fmaf(x0,e.x,d3); d3 = fmaf(x1,e.y,d3); d3 = fmaf(x2,e.z,d3); d3 = fmaf(x3,e.w,d3);
    }
    unsigned long long bl = ~0ull;
    float dj[4] = {d0,d1,d2,d3};
    #pragma unroll
    for (int j=0;j<4;++j){
        float sc = __fsub_rn(__fadd_rn(xnv, __ldg(&g_cnorm[kb+j])), __fmul_rn(2.0f, dj[j]));
        unsigned long long p = ((unsigned long long)f2o(sc)<<32) | (unsigned)(kb+j);
        if (p < bl) bl = p;
    }
    return bl;
}

__global__ void __launch_bounds__(256,3) vq_hmma_kernel(
    const float* __restrict__ x, const float* __restrict__ cb,
    float* __restrict__ out, float* __restrict__ loss_ptr)
{
    extern __shared__ char smc[];
    float*              xs  = (float*)(smc + XS_OFF);
    float*              cns = (float*)(smc + CN_OFF);
    float*              gmS = (float*)(smc + GM_OFF);
    float*              xns = (float*)(smc + XN_OFF);
    float*              tpS = (float*)(smc + TP_OFF);
    float*              thrS= (float*)(smc + TR_OFF);
    unsigned long long* brm = (unsigned long long*)(smc + BM_OFF);
    int*                sid = (int*)(smc + SI_OFF);
    float*              lrd = (float*)(smc + LR_OFF);
    int*                wc  = (int*)(smc + WC_OFF);
    uint16_t*           wl  = (uint16_t*)(smc + B_OFF);   // aliases dead B buffer
    const uint32_t Bu  = s2u(smc + B_OFF);
    const uint32_t CNu = s2u(smc + CN_OFF);

    const int tid = threadIdx.x;
    const int b = blockIdx.x>>6, h = blockIdx.x&63;

    if (tid==0) wc[0] = 0;
    if (tid<64) brm[tid] = ~0ull;

    // ---- load x tile [64d][64w] (coalesced over w) ----
    {
        int w2 = tid&63, d0 = tid>>6;
        const float* xb = x + (size_t)b*DIM*HW + (size_t)h*64 + w2;
        #pragma unroll
        for (int i=0;i<16;i++){ int d = d0*16+i; xs[d*64+w2] = xb[(size_t)d*HW]; }
    }
    __syncthreads();

    // ---- per-row ||x||^2 (mul/add, ascending d) ----
    if (tid<64){
        float s=0.0f;
        #pragma unroll
        for (int d=0; d<DIM; ++d){ float v=xs[d*64+tid]; s=__fadd_rn(s,__fmul_rn(v,v)); }
        xns[tid]=s;
    }

    const int lane = tid&31, w = tid>>5;
    const int g = lane>>2, tg = lane&3;
    const int mbase = (w&3)*16, nh = w>>2;   // 4 m-quarters x 2 n-halves
    const int R0 = mbase+g, R1 = R0+8;
    const uint32_t lds_base = Bu + (uint32_t)(lane&7)*144u + (uint32_t)(lane>>3)*16u;

    // ---- A fragments (one m16 tile per warp, m16n8k16 row-major) ----
    uint32_t afr[4][4];
    #pragma unroll
    for (int ks=0; ks<4; ++ks){
        int c0 = ks*16 + 2*tg, c2 = c0 + 8;
        afr[ks][0] = packbf(xs[c0*64+R0], xs[(c0+1)*64+R0]);
        afr[ks][1] = packbf(xs[c0*64+R1], xs[(c0+1)*64+R1]);
        afr[ks][2] = packbf(xs[c2*64+R0], xs[(c2+1)*64+R0]);
        afr[ks][3] = packbf(xs[c2*64+R1], xs[(c2+1)*64+R1]);
    }

    // ======== single HMMA pass: per-(row, 16k-group) min -> gmS ========
    #pragma unroll 1
    for (int ch=0; ch<4; ++ch){
        {   // stage B chunk via cp.async (256 rows x 128B) + cn
            const uint4* src = ((const uint4*)g_cbb) + ch*2048;
            #pragma unroll
            for (int j=tid; j<2048; j+=256){
                uint32_t dst = Bu + (uint32_t)(j>>3)*144u + (uint32_t)(j&7)*16u;
                CPASYNC16(dst, src + j);
            }
            if (tid<64)
                CPASYNC16(CNu + tid*16u, (const uint4*)(g_cnorm + ch*256) + tid);
            asm volatile("cp.async.commit_group;" ::: "memory");
            asm volatile("cp.async.wait_group 0;" ::: "memory");
        }
        __syncthreads();

        #pragma unroll 1
        for (int it=0; it<4; ++it){
            int n0 = nh*128 + it*32;                  // 4 n8 tiles
            float acc[4][4];
            #pragma unroll
            for (int t=0;t<4;++t){ acc[t][0]=0;acc[t][1]=0;acc[t][2]=0;acc[t][3]=0; }

            #pragma unroll
            for (int pr=0; pr<2; ++pr){
                int t0 = pr*2, t1 = t0+1;
                uint32_t f0[8], f1[8];
                uint32_t a0 = lds_base + (uint32_t)(n0 + 8*t0)*144u;
                uint32_t a1 = lds_base + (uint32_t)(n0 + 8*t1)*144u;
                LDSM4(f0,   a0); LDSM4(f0+4, a0+64u);
                LDSM4(f1,   a1); LDSM4(f1+4, a1+64u);
                #pragma unroll
                for (int ks=0; ks<4; ++ks){
                    HMMA(acc[t0], afr[ks], f0[2*ks], f0[2*ks+1]);
                    HMMA(acc[t1], afr[ks], f1[2*ks], f1[2*ks+1]);
                }
            }

            float s[16];
            #pragma unroll
            for (int t=0;t<4;++t){
                float2 cn2 = *(const float2*)&cns[n0 + 8*t + 2*tg];
                s[t*4+0] = fmaf(-2.0f, acc[t][0], cn2.x);
                s[t*4+1] = fmaf(-2.0f, acc[t][1], cn2.y);
                s[t*4+2] = fmaf(-2.0f, acc[t][2], cn2.x);
                s[t*4+3] = fmaf(-2.0f, acc[t][3], cn2.y);
            }
            int gbase = ch*16 + nh*8 + it*2;
            #pragma unroll
            for (int pr=0; pr<2; ++pr){
                float im0 = fminf(fminf(s[8*pr+0],s[8*pr+1]), fminf(s[8*pr+4],s[8*pr+5]));
                float im1 = fminf(fminf(s[8*pr+2],s[8*pr+3]), fminf(s[8*pr+6],s[8*pr+7]));
                im0 = fminf(im0, __shfl_xor_sync(0xffffffffu, im0, 1));
                im0 = fminf(im0, __shfl_xor_sync(0xffffffffu, im0, 2));
                im1 = fminf(im1, __shfl_xor_sync(0xffffffffu, im1, 1));
                im1 = fminf(im1, __shfl_xor_sync(0xffffffffu, im1, 2));
                if (tg==0){
                    gmS[R0*65 + gbase+pr] = im0;
                    gmS[R1*65 + gbase+pr] = im1;
                }
            }
        }
        __syncthreads();
    }

    // ======== per-row threshold ========
    {
        int row = tid>>2, q = tid&3;
        float m = INF;
        #pragma unroll
        for (int j=0;j<16;++j) m = fminf(m, gmS[row*65 + q + 4*j]);
        tpS[row*4+q] = m;
    }
    __syncthreads();
    if (tid<64)
        thrS[tid] = fminf(fminf(tpS[tid*4],tpS[tid*4+1]),
                          fminf(tpS[tid*4+2],tpS[tid*4+3])) + DELTA;
    __syncthreads();

    // ======== compacted worklist (wl aliases dead B buffer; cap 4096 == max) ====
    {
        int row = tid>>2, q = tid&3;
        float thrv = thrS[row];
        #pragma unroll
        for (int j=0;j<16;++j){
            int gidx = q + 4*j;
            if (gmS[row*65+gidx] < thrv){
                int pos = atomicAdd(wc, 1);
                wl[pos] = (uint16_t)(row*64 + gidx);
            }
        }
    }
    __syncthreads();

    // ======== uniform exact rescore (R1 numerics, MLP-4) ========
    {
        int nw = wc[0];
        int sl = tid&3;
        for (int i = tid>>2; i < nw; i += 64){
            int item = wl[i];
            int row = item>>6, gidx = item&63;
            unsigned long long bl = rescore4(xs, cb, row, gidx*16 + sl*4, xns[row]);
            atomicMin(&brm[row], bl);
        }
    }
    __syncthreads();
    if (tid<64) sid[tid] = (int)(brm[tid] & 0x3FFull);
    __syncthreads();

    // ---- straight-through output + loss (R1 elementwise rounding) ----
    float lsum = 0.0f;
    {
        int w2 = tid&63, d0 = tid>>6;
        int k = sid[w2];
        const float* cr = cb + k*DIM;
        float* ob = out + (size_t)b*DIM*HW + (size_t)h*64 + w2;
        #pragma unroll
        for (int i=0;i<16;i++){
            int d = d0*16+i;
            float q = __ldg(cr+d), xv = xs[d*64+w2];
            float df = __fsub_rn(q, xv);
            lsum = __fadd_rn(lsum, __fmul_rn(df, df));
            ob[(size_t)d*HW] = __fadd_rn(xv, df);
        }
    }
    lrd[tid] = lsum;
    __syncthreads();
    #pragma unroll
    for (int s2=128; s2>0; s2>>=1){
        if (tid<s2) lrd[tid] = __fadd_rn(lrd[tid], lrd[tid+s2]);
        __syncthreads();
    }
    if (tid==0) atomicAdd(loss_ptr, lrd[0] * (1.25f/(float)QELEMS));
}

extern "C" void kernel_launch(void* const* d_in, const int* in_sizes, int n_in,
                              void* d_out, int out_size) {
    const float* x  = (const float*)d_in[0];
    const float* cb = (const float*)d_in[1];
    float* out = (float*)d_out;
    float* loss_ptr = out + (out_size - 1);

    cudaFuncSetAttribute(vq_hmma_kernel, cudaFuncAttributeMaxDynamicSharedMemorySize, SMEM_BYTES);
    vq_prep<<<4, 256>>>(cb, loss_ptr);
    vq_hmma_kernel<<<1024, 256, SMEM_BYTES>>>(x, cb, out, loss_ptr);
}

// round 15
// speedup vs baseline: 1.3067x; 1.0187x over previous
#include <cuda_runtime.h>
#include <cuda_bf16.h>
#include <stdint.h>

#define KTOT 1024
#define DIM  64
#define HW   4096
#define QELEMS 4194304
#define DELTA 2.5e-3f
#define INF __int_as_float(0x7f800000)

// dynamic smem offsets (bytes); B stride = 144 bytes/row (16B-aligned)
#define XS_OFF 0        // f32 xs[64][64]               16384
#define B_OFF  16384    // bf16 B[256][72] (144B rows)  36864
#define CN_OFF 53248    // f32 cn[256]                   1024
#define GM_OFF 54272    // f32 gmin[64][65] padded      16640
#define XN_OFF 70912    // f32 xn[64]                     256
#define TP_OFF 71168    // f32 tp[64][4]                 1024
#define TR_OFF 72192    // f32 thr[64]                    256
#define BM_OFF 72448    // u64 brm[64]                    512
#define SI_OFF 72960    // i32 sid[64]                    256
#define LR_OFF 73216    // f32 lred[256]                 1024
#define WC_OFF 74240    // i32 wcnt                        16
#define SMEM_BYTES 74256
// After the GEMM pass the B buffer is dead and is reused:
//   [B_OFF, B_OFF+30016)   rescore staging: 7 items x 1072 words (4288B)
//   [B_OFF+30720, +4096B)  worklist wl[2048] u16
#define WL_BYTE_OFF (B_OFF + 30720)
#define WL_CAP 2048

__device__ float g_cnorm[KTOT];
__device__ __align__(16) __nv_bfloat16 g_cbb[KTOT*DIM];

__global__ void vq_prep(const float* __restrict__ cb, float* __restrict__ loss_ptr){
    int k = blockIdx.x*256 + threadIdx.x;
    if (k==0) *loss_ptr = 0.0f;
    if (k < KTOT){
        float s = 0.0f;
        #pragma unroll
        for (int d=0; d<DIM; ++d){
            float c = cb[k*DIM+d];
            g_cbb[k*DIM+d] = __float2bfloat16(c);
            s = __fadd_rn(s, __fmul_rn(c,c));
        }
        g_cnorm[k] = s;
    }
}

__device__ __forceinline__ uint32_t packbf(float lo, float hi){
    __nv_bfloat162 h = __floats2bfloat162_rn(lo, hi);
    return *(uint32_t*)&h;
}
__device__ __forceinline__ uint32_t f2o(float f){
    uint32_t u = __float_as_uint(f);
    return (u & 0x80000000u) ? ~u : (u | 0x80000000u);
}
__device__ __forceinline__ uint32_t s2u(const void* p){
    uint32_t a; asm("{ .reg .u64 t; cvta.to.shared.u64 t, %1; cvt.u32.u64 %0, t; }":"=r"(a):"l"(p)); return a;
}
#define HMMA(acc,a,b0,b1) asm volatile( \
    "mma.sync.aligned.m16n8k16.row.col.f32.bf16.bf16.f32 " \
    "{%0,%1,%2,%3}, {%4,%5,%6,%7}, {%8,%9}, {%0,%1,%2,%3};" \
    : "+f"((acc)[0]),"+f"((acc)[1]),"+f"((acc)[2]),"+f"((acc)[3]) \
    : "r"((a)[0]),"r"((a)[1]),"r"((a)[2]),"r"((a)[3]), "r"(b0),"r"(b1))
#define LDSM4(r,a) asm volatile( \
    "ldmatrix.sync.aligned.m8n8.x4.shared.b16 {%0,%1,%2,%3}, [%4];" \
    : "=r"((r)[0]),"=r"((r)[1]),"=r"((r)[2]),"=r"((r)[3]) : "r"(a))
#define CPASYNC16(dst,src) asm volatile( \
    "cp.async.cg.shared.global [%0], [%1], 16;" :: "r"(dst), "l"(src))

__global__ void __launch_bounds__(256,3) vq_hmma_kernel(
    const float* __restrict__ x, const float* __restrict__ cb,
    float* __restrict__ out, float* __restrict__ loss_ptr)
{
    extern __shared__ char smc[];
    float*              xs  = (float*)(smc + XS_OFF);
    float*              cns = (float*)(smc + CN_OFF);
    float*              gmS = (float*)(smc + GM_OFF);
    float*              xns = (float*)(smc + XN_OFF);
    float*              tpS = (float*)(smc + TP_OFF);
    float*              thrS= (float*)(smc + TR_OFF);
    unsigned long long* brm = (unsigned long long*)(smc + BM_OFF);
    int*                sid = (int*)(smc + SI_OFF);
    float*              lrd = (float*)(smc + LR_OFF);
    int*                wc  = (int*)(smc + WC_OFF);
    uint16_t*           wl  = (uint16_t*)(smc + WL_BYTE_OFF); // B-tail, dead after GEMM
    float*              stg = (float*)(smc + B_OFF);          // rescore staging
    const uint32_t Bu  = s2u(smc + B_OFF);
    const uint32_t CNu = s2u(smc + CN_OFF);

    const int tid = threadIdx.x;
    const int b = blockIdx.x>>6, h = blockIdx.x&63;

    if (tid==0) wc[0] = 0;
    if (tid<64) brm[tid] = ~0ull;

    // ---- load x tile [64d][64w] (coalesced over w) ----
    {
        int w2 = tid&63, d0 = tid>>6;
        const float* xb = x + (size_t)b*DIM*HW + (size_t)h*64 + w2;
        #pragma unroll
        for (int i=0;i<16;i++){ int d = d0*16+i; xs[d*64+w2] = xb[(size_t)d*HW]; }
    }
    __syncthreads();

    // ---- per-row ||x||^2 (mul/add, ascending d) ----
    if (tid<64){
        float s=0.0f;
        #pragma unroll
        for (int d=0; d<DIM; ++d){ float v=xs[d*64+tid]; s=__fadd_rn(s,__fmul_rn(v,v)); }
        xns[tid]=s;
    }

    const int lane = tid&31, w = tid>>5;
    const int g = lane>>2, tg = lane&3;
    const int mbase = (w&3)*16, nh = w>>2;   // 4 m-quarters x 2 n-halves
    const int R0 = mbase+g, R1 = R0+8;
    const uint32_t lds_base = Bu + (uint32_t)(lane&7)*144u + (uint32_t)(lane>>3)*16u;

    // ---- A fragments (one m16 tile per warp, m16n8k16 row-major) ----
    uint32_t afr[4][4];
    #pragma unroll
    for (int ks=0; ks<4; ++ks){
        int c0 = ks*16 + 2*tg, c2 = c0 + 8;
        afr[ks][0] = packbf(xs[c0*64+R0], xs[(c0+1)*64+R0]);
        afr[ks][1] = packbf(xs[c0*64+R1], xs[(c0+1)*64+R1]);
        afr[ks][2] = packbf(xs[c2*64+R0], xs[(c2+1)*64+R0]);
        afr[ks][3] = packbf(xs[c2*64+R1], xs[(c2+1)*64+R1]);
    }

    // ======== single HMMA pass: per-(row, 16k-group) min -> gmS ========
    #pragma unroll 1
    for (int ch=0; ch<4; ++ch){
        {   // stage B chunk via cp.async (256 rows x 128B) + cn
            const uint4* src = ((const uint4*)g_cbb) + ch*2048;
            #pragma unroll
            for (int j=tid; j<2048; j+=256){
                uint32_t dst = Bu + (uint32_t)(j>>3)*144u + (uint32_t)(j&7)*16u;
                CPASYNC16(dst, src + j);
            }
            if (tid<64)
                CPASYNC16(CNu + tid*16u, (const uint4*)(g_cnorm + ch*256) + tid);
            asm volatile("cp.async.commit_group;" ::: "memory");
            asm volatile("cp.async.wait_group 0;" ::: "memory");
        }
        __syncthreads();

        #pragma unroll 1
        for (int it=0; it<4; ++it){
            int n0 = nh*128 + it*32;                  // 4 n8 tiles
            float acc[4][4];
            #pragma unroll
            for (int t=0;t<4;++t){ acc[t][0]=0;acc[t][1]=0;acc[t][2]=0;acc[t][3]=0; }

            #pragma unroll
            for (int pr=0; pr<2; ++pr){
                int t0 = pr*2, t1 = t0+1;
                uint32_t f0[8], f1[8];
                uint32_t a0 = lds_base + (uint32_t)(n0 + 8*t0)*144u;
                uint32_t a1 = lds_base + (uint32_t)(n0 + 8*t1)*144u;
                LDSM4(f0,   a0); LDSM4(f0+4, a0+64u);
                LDSM4(f1,   a1); LDSM4(f1+4, a1+64u);
                #pragma unroll
                for (int ks=0; ks<4; ++ks){
                    HMMA(acc[t0], afr[ks], f0[2*ks], f0[2*ks+1]);
                    HMMA(acc[t1], afr[ks], f1[2*ks], f1[2*ks+1]);
                }
            }

            float s[16];
            #pragma unroll
            for (int t=0;t<4;++t){
                float2 cn2 = *(const float2*)&cns[n0 + 8*t + 2*tg];
                s[t*4+0] = fmaf(-2.0f, acc[t][0], cn2.x);
                s[t*4+1] = fmaf(-2.0f, acc[t][1], cn2.y);
                s[t*4+2] = fmaf(-2.0f, acc[t][2], cn2.x);
                s[t*4+3] = fmaf(-2.0f, acc[t][3], cn2.y);
            }
            int gbase = ch*16 + nh*8 + it*2;
            #pragma unroll
            for (int pr=0; pr<2; ++pr){
                float im0 = fminf(fminf(s[8*pr+0],s[8*pr+1]), fminf(s[8*pr+4],s[8*pr+5]));
                float im1 = fminf(fminf(s[8*pr+2],s[8*pr+3]), fminf(s[8*pr+6],s[8*pr+7]));
                im0 = fminf(im0, __shfl_xor_sync(0xffffffffu, im0, 1));
                im0 = fminf(im0, __shfl_xor_sync(0xffffffffu, im0, 2));
                im1 = fminf(im1, __shfl_xor_sync(0xffffffffu, im1, 1));
                im1 = fminf(im1, __shfl_xor_sync(0xffffffffu, im1, 2));
                if (tg==0){
                    gmS[R0*65 + gbase+pr] = im0;
                    gmS[R1*65 + gbase+pr] = im1;
                }
            }
        }
        __syncthreads();
    }

    // ======== per-row threshold ========
    {
        int row = tid>>2, q = tid&3;
        float m = INF;
        #pragma unroll
        for (int j=0;j<16;++j) m = fminf(m, gmS[row*65 + q + 4*j]);
        tpS[row*4+q] = m;
    }
    __syncthreads();
    if (tid<64)
        thrS[tid] = fminf(fminf(tpS[tid*4],tpS[tid*4+1]),
                          fminf(tpS[tid*4+2],tpS[tid*4+3])) + DELTA;
    __syncthreads();

    // ======== compacted worklist (B-tail; overflow -> deterministic full list) ==
    {
        int row = tid>>2, q = tid&3;
        float thrv = thrS[row];
        #pragma unroll
        for (int j=0;j<16;++j){
            int gidx = q + 4*j;
            if (gmS[row*65+gidx] < thrv){
                int pos = atomicAdd(wc, 1);
                if (pos < WL_CAP) wl[pos] = (uint16_t)(row*64 + gidx);
            }
        }
    }
    __syncthreads();

    // ======== staged exact rescore (R1 numerics), coalesced gather ========
    {
        int nw = wc[0];
        bool full = (nw > WL_CAP);          // degenerate input only; deterministic
        int nwEff = full ? 4096 : nw;
        #pragma unroll 1
        for (int base = 0; base < nwEff; base += 7){
            int nit = nwEff - base; if (nit > 7) nit = 7;
            // stage nit items: each item = 16 contiguous fp32 cb rows = 4KB
            #pragma unroll 1
            for (int c = tid; c < nit*256; c += 256){
                int it2 = c >> 8;
                int idx = base + it2;
                int item = full ? idx : (int)wl[idx];
                int gidx = item & 63;
                uint4 v = __ldg(((const uint4*)cb) + (gidx*256 + (c & 255)));
                int j = (c >> 4) & 15, dq = (c & 15) * 4;
                float* dstp = stg + it2*1072 + j*67 + dq;
                dstp[0] = __uint_as_float(v.x);
                dstp[1] = __uint_as_float(v.y);
                dstp[2] = __uint_as_float(v.z);
                dstp[3] = __uint_as_float(v.w);
            }
            __syncthreads();
            if (tid < nit*16){
                int it2 = tid >> 4, j = tid & 15;
                int idx = base + it2;
                int item = full ? idx : (int)wl[idx];
                int row = item >> 6, gidx = item & 63;
                int k = gidx*16 + j;
                const float* cs2 = stg + it2*1072 + j*67;
                float dot = 0.0f;
                #pragma unroll
                for (int d = 0; d < 64; ++d)
                    dot = fmaf(xs[d*64 + row], cs2[d], dot);
                float sc = __fsub_rn(__fadd_rn(xns[row], __ldg(&g_cnorm[k])),
                                     __fmul_rn(2.0f, dot));
                unsigned long long p = ((unsigned long long)f2o(sc)<<32) | (unsigned)k;
                atomicMin(&brm[row], p);
            }
            __syncthreads();
        }
    }

    if (tid<64) sid[tid] = (int)(brm[tid] & 0x3FFull);
    __syncthreads();

    // ---- straight-through output + loss (R1 elementwise rounding) ----
    float lsum = 0.0f;
    {
        int w2 = tid&63, d0 = tid>>6;
        int k = sid[w2];
        const float* cr = cb + k*DIM;
        float* ob = out + (size_t)b*DIM*HW + (size_t)h*64 + w2;
        #pragma unroll
        for (int i=0;i<16;i++){
            int d = d0*16+i;
            float q = __ldg(cr+d), xv = xs[d*64+w2];
            float df = __fsub_rn(q, xv);
            lsum = __fadd_rn(lsum, __fmul_rn(df, df));
            ob[(size_t)d*HW] = __fadd_rn(xv, df);
        }
    }
    lrd[tid] = lsum;
    __syncthreads();
    #pragma unroll
    for (int s2=128; s2>0; s2>>=1){
        if (tid<s2) lrd[tid] = __fadd_rn(lrd[tid], lrd[tid+s2]);
        __syncthreads();
    }
    if (tid==0) atomicAdd(loss_ptr, lrd[0] * (1.25f/(float)QELEMS));
}

extern "C" void kernel_launch(void* const* d_in, const int* in_sizes, int n_in,
                              void* d_out, int out_size) {
    const float* x  = (const float*)d_in[0];
    const float* cb = (const float*)d_in[1];
    float* out = (float*)d_out;
    float* loss_ptr = out + (out_size - 1);

    cudaFuncSetAttribute(vq_hmma_kernel, cudaFuncAttributeMaxDynamicSharedMemorySize, SMEM_BYTES);
    vq_prep<<<4, 256>>>(cb, loss_ptr);
    vq_hmma_kernel<<<1024, 256, SMEM_BYTES>>>(x, cb, out, loss_ptr);
}

// round 16
// speedup vs baseline: 2.5549x; 1.9552x over previous
#include <cuda_runtime.h>
#include <cuda_bf16.h>
#include <stdint.h>

#define KTOT 1024
#define DIM  64
#define HW   4096
#define QELEMS 4194304
#define DELTA 2.5e-3f
#define INF __int_as_float(0x7f800000)

// dynamic smem offsets (bytes); B stride = 144 bytes/row (16B-aligned)
#define XS_OFF 0        // f32 xs[64][64]               16384
#define B_OFF  16384    // bf16 B[256][72] (144B rows)  36864
#define CN_OFF 53248    // f32 cn[256]                   1024
#define XN_OFF 54272    // f32 xn[64]                     256
#define TH_OFF 54528    // f32 thp[64][2]                 512
#define TR_OFF 55040    // f32 thr[64]                    256
#define BM_OFF 55296    // u64 brm[64]                    512
#define SI_OFF 55808    // i32 sid[64]                    256
#define LR_OFF 56064    // f32 lred[256]                 1024
#define WC_OFF 57088    // i32 wcnt                        16
#define WL_OFF 57104    // u16 wl[2048]                  4096
#define SMEM_BYTES 61200
#define WL_CAP 2048
// rescore staging (after both GEMM passes) aliases the dead B buffer:
// 128 items x 67 f32 (stride-67 => conflict-free chain LDS) = 34304 B <= 36864

__device__ float g_cnorm[KTOT];
__device__ __align__(16) __nv_bfloat16 g_cbb[KTOT*DIM];

__global__ void vq_prep(const float* __restrict__ cb, float* __restrict__ loss_ptr){
    int k = blockIdx.x*256 + threadIdx.x;
    if (k==0) *loss_ptr = 0.0f;
    if (k < KTOT){
        float s = 0.0f;
        #pragma unroll
        for (int d=0; d<DIM; ++d){
            float c = cb[k*DIM+d];
            g_cbb[k*DIM+d] = __float2bfloat16(c);
            s = __fadd_rn(s, __fmul_rn(c,c));
        }
        g_cnorm[k] = s;
    }
}

__device__ __forceinline__ uint32_t packbf(float lo, float hi){
    __nv_bfloat162 h = __floats2bfloat162_rn(lo, hi);
    return *(uint32_t*)&h;
}
__device__ __forceinline__ uint32_t f2o(float f){
    uint32_t u = __float_as_uint(f);
    return (u & 0x80000000u) ? ~u : (u | 0x80000000u);
}
__device__ __forceinline__ uint32_t s2u(const void* p){
    uint32_t a; asm("{ .reg .u64 t; cvta.to.shared.u64 t, %1; cvt.u32.u64 %0, t; }":"=r"(a):"l"(p)); return a;
}
#define HMMA(acc,a,b0,b1) asm volatile( \
    "mma.sync.aligned.m16n8k16.row.col.f32.bf16.bf16.f32 " \
    "{%0,%1,%2,%3}, {%4,%5,%6,%7}, {%8,%9}, {%0,%1,%2,%3};" \
    : "+f"((acc)[0]),"+f"((acc)[1]),"+f"((acc)[2]),"+f"((acc)[3]) \
    : "r"((a)[0]),"r"((a)[1]),"r"((a)[2]),"r"((a)[3]), "r"(b0),"r"(b1))
#define LDSM4(r,a) asm volatile( \
    "ldmatrix.sync.aligned.m8n8.x4.shared.b16 {%0,%1,%2,%3}, [%4];" \
    : "=r"((r)[0]),"=r"((r)[1]),"=r"((r)[2]),"=r"((r)[3]) : "r"(a))
#define CPASYNC16(dst,src) asm volatile( \
    "cp.async.cg.shared.global [%0], [%1], 16;" :: "r"(dst), "l"(src))

__global__ void __launch_bounds__(256,3) vq_hmma_kernel(
    const float* __restrict__ x, const float* __restrict__ cb,
    float* __restrict__ out, float* __restrict__ loss_ptr)
{
    extern __shared__ char smc[];
    float*              xs  = (float*)(smc + XS_OFF);
    float*              cns = (float*)(smc + CN_OFF);
    float*              xns = (float*)(smc + XN_OFF);
    float*              thp = (float*)(smc + TH_OFF);
    float*              thrS= (float*)(smc + TR_OFF);
    unsigned long long* brm = (unsigned long long*)(smc + BM_OFF);
    int*                sid = (int*)(smc + SI_OFF);
    float*              lrd = (float*)(smc + LR_OFF);
    int*                wc  = (int*)(smc + WC_OFF);
    uint16_t*           wl  = (uint16_t*)(smc + WL_OFF);
    float*              stg = (float*)(smc + B_OFF);   // aliases dead B buffer
    const uint32_t Bu  = s2u(smc + B_OFF);
    const uint32_t CNu = s2u(smc + CN_OFF);

    const int tid = threadIdx.x;
    const int b = blockIdx.x>>6, h = blockIdx.x&63;

    if (tid==0) wc[0] = 0;
    if (tid<64) brm[tid] = ~0ull;

    // ---- load x tile [64d][64w] (coalesced over w) ----
    {
        int w2 = tid&63, d0 = tid>>6;
        const float* xb = x + (size_t)b*DIM*HW + (size_t)h*64 + w2;
        #pragma unroll
        for (int i=0;i<16;i++){ int d = d0*16+i; xs[d*64+w2] = xb[(size_t)d*HW]; }
    }
    __syncthreads();

    // ---- per-row ||x||^2 (mul/add, ascending d) ----
    if (tid<64){
        float s=0.0f;
        #pragma unroll
        for (int d=0; d<DIM; ++d){ float v=xs[d*64+tid]; s=__fadd_rn(s,__fmul_rn(v,v)); }
        xns[tid]=s;
    }

    const int lane = tid&31, w = tid>>5;
    const int g = lane>>2, tg = lane&3;
    const int mbase = (w&3)*16, nh = w>>2;   // 4 m-quarters x 2 n-halves
    const int R0 = mbase+g, R1 = R0+8;
    const uint32_t lds_base = Bu + (uint32_t)(lane&7)*144u + (uint32_t)(lane>>3)*16u;

    // ---- A fragments (one m16 tile per warp, m16n8k16 row-major) ----
    uint32_t afr[4][4];
    #pragma unroll
    for (int ks=0; ks<4; ++ks){
        int c0 = ks*16 + 2*tg, c2 = c0 + 8;
        afr[ks][0] = packbf(xs[c0*64+R0], xs[(c0+1)*64+R0]);
        afr[ks][1] = packbf(xs[c0*64+R1], xs[(c0+1)*64+R1]);
        afr[ks][2] = packbf(xs[c2*64+R0], xs[(c2+1)*64+R0]);
        afr[ks][3] = packbf(xs[c2*64+R1], xs[(c2+1)*64+R1]);
    }

    float rm0 = INF, rm1 = INF;
    float thr0 = 0.0f, thr1 = 0.0f;

    // ======== two GEMM passes: pass0 = per-row min, pass1 = per-k hit append ====
    for (int pass=0; pass<2; ++pass){
        if (pass==1){
            rm0 = fminf(rm0, __shfl_xor_sync(0xffffffffu, rm0, 1));
            rm0 = fminf(rm0, __shfl_xor_sync(0xffffffffu, rm0, 2));
            rm1 = fminf(rm1, __shfl_xor_sync(0xffffffffu, rm1, 1));
            rm1 = fminf(rm1, __shfl_xor_sync(0xffffffffu, rm1, 2));
            if (tg==0){ thp[R0*2+nh] = rm0; thp[R1*2+nh] = rm1; }
            __syncthreads();
            if (tid<64) thrS[tid] = fminf(thp[tid*2], thp[tid*2+1]) + DELTA;
            __syncthreads();
            thr0 = thrS[R0]; thr1 = thrS[R1];
        }

        #pragma unroll 1
        for (int c=0; c<4; ++c){
            // pass0: chunks 0..3; pass1: 3..0 (chunk 3 still resident -> skip stage)
            const int ch = (pass==0) ? c : (3-c);
            if (!(pass==1 && c==0)){
                const uint4* src = ((const uint4*)g_cbb) + ch*2048;
                #pragma unroll
                for (int j=tid; j<2048; j+=256){
                    uint32_t dst = Bu + (uint32_t)(j>>3)*144u + (uint32_t)(j&7)*16u;
                    CPASYNC16(dst, src + j);
                }
                if (tid<64)
                    CPASYNC16(CNu + tid*16u, (const uint4*)(g_cnorm + ch*256) + tid);
                asm volatile("cp.async.commit_group;" ::: "memory");
                asm volatile("cp.async.wait_group 0;" ::: "memory");
                __syncthreads();
            }

            #pragma unroll 1
            for (int it=0; it<4; ++it){
                int n0 = nh*128 + it*32;                  // 4 n8 tiles
                float acc[4][4];
                #pragma unroll
                for (int t=0;t<4;++t){ acc[t][0]=0;acc[t][1]=0;acc[t][2]=0;acc[t][3]=0; }

                #pragma unroll
                for (int pr=0; pr<2; ++pr){
                    int t0 = pr*2, t1 = t0+1;
                    uint32_t f0[8], f1[8];
                    uint32_t a0 = lds_base + (uint32_t)(n0 + 8*t0)*144u;
                    uint32_t a1 = lds_base + (uint32_t)(n0 + 8*t1)*144u;
                    LDSM4(f0,   a0); LDSM4(f0+4, a0+64u);
                    LDSM4(f1,   a1); LDSM4(f1+4, a1+64u);
                    #pragma unroll
                    for (int ks=0; ks<4; ++ks){
                        HMMA(acc[t0], afr[ks], f0[2*ks], f0[2*ks+1]);
                        HMMA(acc[t1], afr[ks], f1[2*ks], f1[2*ks+1]);
                    }
                }

                float s[16];
                #pragma unroll
                for (int t=0;t<4;++t){
                    float2 cn2 = *(const float2*)&cns[n0 + 8*t + 2*tg];
                    s[t*4+0] = fmaf(-2.0f, acc[t][0], cn2.x);
                    s[t*4+1] = fmaf(-2.0f, acc[t][1], cn2.y);
                    s[t*4+2] = fmaf(-2.0f, acc[t][2], cn2.x);
                    s[t*4+3] = fmaf(-2.0f, acc[t][3], cn2.y);
                }
                float im0 = fminf(fminf(s[0],s[1]),  fminf(s[4],s[5]));
                im0 = fminf(im0, fminf(fminf(s[8],s[9]),  fminf(s[12],s[13])));
                float im1 = fminf(fminf(s[2],s[3]),  fminf(s[6],s[7]));
                im1 = fminf(im1, fminf(fminf(s[10],s[11]),fminf(s[14],s[15])));

                if (pass==0){
                    rm0 = fminf(rm0, im0);
                    rm1 = fminf(rm1, im1);
                } else {
                    bool hit = (im0 < thr0) | (im1 < thr1);
                    if (__any_sync(0xffffffffu, hit)){
                        #pragma unroll
                        for (int t=0;t<4;++t){
                            #pragma unroll
                            for (int e=0;e<2;++e){
                                int k = ch*256 + n0 + 8*t + 2*tg + e;
                                if (s[t*4+e] < thr0){
                                    int pos = atomicAdd(wc, 1);
                                    if (pos < WL_CAP) wl[pos] = (uint16_t)((R0<<10) | k);
                                }
                                if (s[t*4+2+e] < thr1){
                                    int pos = atomicAdd(wc, 1);
                                    if (pos < WL_CAP) wl[pos] = (uint16_t)((R1<<10) | k);
                                }
                            }
                        }
                    }
                }
            }
            __syncthreads();   // B consumed before next chunk overwrite
        }
    }

    // ======== staged exact rescore (R1 numerics): 128 items per round ========
    {
        int nwRaw = wc[0];
        if (nwRaw <= WL_CAP){
            #pragma unroll 1
            for (int base = 0; base < nwRaw; base += 128){
                int nit = nwRaw - base; if (nit > 128) nit = 128;
                // coalesced gather: each item's fp32 cb row (256B) -> stride-67 smem
                #pragma unroll 1
                for (int c2 = tid; c2 < nit*16; c2 += 256){
                    int it2 = c2 >> 4, part = c2 & 15;
                    int k = wl[base+it2] & 1023;
                    uint4 v = __ldg(((const uint4*)cb) + k*16 + part);
                    float* dp = stg + it2*67 + part*4;
                    dp[0] = __uint_as_float(v.x);
                    dp[1] = __uint_as_float(v.y);
                    dp[2] = __uint_as_float(v.z);
                    dp[3] = __uint_as_float(v.w);
                }
                __syncthreads();
                if (tid < nit){
                    int item = wl[base+tid];
                    int row = item >> 10, k = item & 1023;
                    const float* cs2 = stg + tid*67;
                    float dot = 0.0f;
                    #pragma unroll
                    for (int d = 0; d < 64; ++d)
                        dot = fmaf(xs[d*64 + row], cs2[d], dot);
                    float sc = __fsub_rn(__fadd_rn(xns[row], __ldg(&g_cnorm[k])),
                                         __fmul_rn(2.0f, dot));
                    unsigned long long p = ((unsigned long long)f2o(sc)<<32) | (unsigned)k;
                    atomicMin(&brm[row], p);
                }
                __syncthreads();
            }
        } else {
            // deterministic full fallback (degenerate inputs only)
            int row = tid&63, q = tid>>6;
            float xnv = xns[row];
            #pragma unroll 1
            for (int k = q*256; k < q*256+256; ++k){
                const float4* cr = (const float4*)(cb + k*DIM);
                float dot = 0.0f;
                #pragma unroll
                for (int qq=0; qq<16; ++qq){
                    float4 cv = __ldg(cr+qq);
                    int dd = qq*4;
                    dot = fmaf(xs[dd*64+row],     cv.x, dot);
                    dot = fmaf(xs[(dd+1)*64+row], cv.y, dot);
                    dot = fmaf(xs[(dd+2)*64+row], cv.z, dot);
                    dot = fmaf(xs[(dd+3)*64+row], cv.w, dot);
                }
                float sc = __fsub_rn(__fadd_rn(xnv, __ldg(&g_cnorm[k])),
                                     __fmul_rn(2.0f, dot));
                unsigned long long p = ((unsigned long long)f2o(sc)<<32) | (unsigned)k;
                atomicMin(&brm[row], p);
            }
            __syncthreads();
        }
    }

    if (tid<64) sid[tid] = (int)(brm[tid] & 0x3FFull);
    __syncthreads();

    // ---- straight-through output + loss (R1 elementwise rounding) ----
    float lsum = 0.0f;
    {
        int w2 = tid&63, d0 = tid>>6;
        int k = sid[w2];
        const float* cr = cb + k*DIM;
        float* ob = out + (size_t)b*DIM*HW + (size_t)h*64 + w2;
        #pragma unroll
        for (int i=0;i<16;i++){
            int d = d0*16+i;
            float q = __ldg(cr+d), xv = xs[d*64+w2];
            float df = __fsub_rn(q, xv);
            lsum = __fadd_rn(lsum, __fmul_rn(df, df));
            ob[(size_t)d*HW] = __fadd_rn(xv, df);
        }
    }
    lrd[tid] = lsum;
    __syncthreads();
    #pragma unroll
    for (int s2=128; s2>0; s2>>=1){
        if (tid<s2) lrd[tid] = __fadd_rn(lrd[tid], lrd[tid+s2]);
        __syncthreads();
    }
    if (tid==0) atomicAdd(loss_ptr, lrd[0] * (1.25f/(float)QELEMS));
}

extern "C" void kernel_launch(void* const* d_in, const int* in_sizes, int n_in,
                              void* d_out, int out_size) {
    const float* x  = (const float*)d_in[0];
    const float* cb = (const float*)d_in[1];
    float* out = (float*)d_out;
    float* loss_ptr = out + (out_size - 1);

    cudaFuncSetAttribute(vq_hmma_kernel, cudaFuncAttributeMaxDynamicSharedMemorySize, SMEM_BYTES);
    vq_prep<<<4, 256>>>(cb, loss_ptr);
    vq_hmma_kernel<<<1024, 256, SMEM_BYTES>>>(x, cb, out, loss_ptr);
}

// round 17
// speedup vs baseline: 2.8614x; 1.1200x over previous
#include <cuda_runtime.h>
#include <cuda_bf16.h>
#include <stdint.h>

#define KTOT 1024
#define DIM  64
#define HW   4096
#define QELEMS 4194304
#define DELTA 2.5e-3f
#define INF __int_as_float(0x7f800000)

// dynamic smem offsets (bytes); B stride = 144 bytes/row (16B-aligned)
#define XS_OFF 0        // f32 xs[64][64]               16384
#define B_OFF  16384    // bf16 B[256][72] (144B rows)  36864
#define CN_OFF 53248    // f32 cn[256]                   1024
#define XN_OFF 54272    // f32 xn[64]                     256
#define TH_OFF 54528    // f32 thp[64][4]                1024
#define TR_OFF 55552    // f32 thr[64]                    256
#define BM_OFF 55808    // u64 brm[64]                    512
#define SI_OFF 56320    // i32 sid[64]                    256
#define LR_OFF 56576    // f32 lred[256]                 1024
#define WC_OFF 57600    // i32 wcnt                        16
#define WL_OFF 57616    // u16 wl[2048]                  4096
#define SMEM_BYTES 61712
#define WL_CAP 2048
// stg (rescore 128x67 f32 = 34304B; then epilogue qs 64x67 f32) aliases dead B

__device__ float g_cnorm[KTOT];
__device__ __align__(16) __nv_bfloat16 g_cbb[KTOT*DIM];

__global__ void vq_prep(const float* __restrict__ cb, float* __restrict__ loss_ptr){
    int k = blockIdx.x*256 + threadIdx.x;
    if (k==0) *loss_ptr = 0.0f;
    if (k < KTOT){
        float s = 0.0f;
        #pragma unroll
        for (int d=0; d<DIM; ++d){
            float c = cb[k*DIM+d];
            g_cbb[k*DIM+d] = __float2bfloat16(c);
            s = __fadd_rn(s, __fmul_rn(c,c));
        }
        g_cnorm[k] = s;
    }
}

__device__ __forceinline__ uint32_t packbf(float lo, float hi){
    __nv_bfloat162 h = __floats2bfloat162_rn(lo, hi);
    return *(uint32_t*)&h;
}
__device__ __forceinline__ uint32_t f2o(float f){
    uint32_t u = __float_as_uint(f);
    return (u & 0x80000000u) ? ~u : (u | 0x80000000u);
}
__device__ __forceinline__ uint32_t s2u(const void* p){
    uint32_t a; asm("{ .reg .u64 t; cvta.to.shared.u64 t, %1; cvt.u32.u64 %0, t; }":"=r"(a):"l"(p)); return a;
}
#define HMMA(acc,a,b0,b1) asm volatile( \
    "mma.sync.aligned.m16n8k16.row.col.f32.bf16.bf16.f32 " \
    "{%0,%1,%2,%3}, {%4,%5,%6,%7}, {%8,%9}, {%0,%1,%2,%3};" \
    : "+f"((acc)[0]),"+f"((acc)[1]),"+f"((acc)[2]),"+f"((acc)[3]) \
    : "r"((a)[0]),"r"((a)[1]),"r"((a)[2]),"r"((a)[3]), "r"(b0),"r"(b1))
#define LDSM4(r,a) asm volatile( \
    "ldmatrix.sync.aligned.m8n8.x4.shared.b16 {%0,%1,%2,%3}, [%4];" \
    : "=r"((r)[0]),"=r"((r)[1]),"=r"((r)[2]),"=r"((r)[3]) : "r"(a))
#define CPASYNC16(dst,src) asm volatile( \
    "cp.async.cg.shared.global [%0], [%1], 16;" :: "r"(dst), "l"(src))

__global__ void __launch_bounds__(256,3) vq_hmma_kernel(
    const float* __restrict__ x, const float* __restrict__ cb,
    float* __restrict__ out, float* __restrict__ loss_ptr)
{
    extern __shared__ char smc[];
    float*              xs  = (float*)(smc + XS_OFF);
    float*              cns = (float*)(smc + CN_OFF);
    float*              xns = (float*)(smc + XN_OFF);
    float*              thp = (float*)(smc + TH_OFF);
    float*              thrS= (float*)(smc + TR_OFF);
    unsigned long long* brm = (unsigned long long*)(smc + BM_OFF);
    int*                sid = (int*)(smc + SI_OFF);
    float*              lrd = (float*)(smc + LR_OFF);
    int*                wc  = (int*)(smc + WC_OFF);
    uint16_t*           wl  = (uint16_t*)(smc + WL_OFF);
    float*              stg = (float*)(smc + B_OFF);   // aliases dead B buffer
    const uint32_t Bu  = s2u(smc + B_OFF);
    const uint32_t CNu = s2u(smc + CN_OFF);

    const int tid = threadIdx.x;
    const int b = blockIdx.x>>6, h = blockIdx.x&63;

    if (tid==0) wc[0] = 0;
    if (tid<64) brm[tid] = ~0ull;

    // ---- load x tile [64d][64w] (coalesced over w) ----
    {
        int w2 = tid&63, d0 = tid>>6;
        const float* xb = x + (size_t)b*DIM*HW + (size_t)h*64 + w2;
        #pragma unroll
        for (int i=0;i<16;i++){ int d = d0*16+i; xs[d*64+w2] = xb[(size_t)d*HW]; }
    }
    __syncthreads();

    // ---- per-row ||x||^2 (mul/add, ascending d) ----
    if (tid<64){
        float s=0.0f;
        #pragma unroll
        for (int d=0; d<DIM; ++d){ float v=xs[d*64+tid]; s=__fadd_rn(s,__fmul_rn(v,v)); }
        xns[tid]=s;
    }

    const int lane = tid&31, w = tid>>5;
    const int g = lane>>2, tg = lane&3;
    const int mhalf = (w&1)*32, nq = w>>1;   // 2 m-halves x 4 n-quarters
    const int R[4] = { mhalf+g, mhalf+8+g, mhalf+16+g, mhalf+24+g };
    const uint32_t lds_base = Bu + (uint32_t)(lane&7)*144u + (uint32_t)(lane>>3)*16u;

    // ---- A fragments: TWO m16 tiles per warp (R5-validated mapping) ----
    uint32_t afr[2][4][4];
    #pragma unroll
    for (int mt=0; mt<2; ++mt)
        #pragma unroll
        for (int ks=0; ks<4; ++ks){
            int R0t = mhalf + mt*16 + g, R1t = R0t + 8;
            int c0 = ks*16 + 2*tg, c2 = c0 + 8;
            afr[mt][ks][0] = packbf(xs[c0*64+R0t], xs[(c0+1)*64+R0t]);
            afr[mt][ks][1] = packbf(xs[c0*64+R1t], xs[(c0+1)*64+R1t]);
            afr[mt][ks][2] = packbf(xs[c2*64+R0t], xs[(c2+1)*64+R0t]);
            afr[mt][ks][3] = packbf(xs[c2*64+R1t], xs[(c2+1)*64+R1t]);
        }

    float rm[4] = {INF,INF,INF,INF};
    float thr[4] = {0,0,0,0};

    // ======== two GEMM passes: pass0 = per-row min, pass1 = per-k hit append ====
    for (int pass=0; pass<2; ++pass){
        if (pass==1){
            #pragma unroll
            for (int lr=0; lr<4; ++lr){
                float v = rm[lr];
                v = fminf(v, __shfl_xor_sync(0xffffffffu, v, 1));
                v = fminf(v, __shfl_xor_sync(0xffffffffu, v, 2));
                if (tg==0) thp[R[lr]*4 + nq] = v;
            }
            __syncthreads();
            if (tid<64)
                thrS[tid] = fminf(fminf(thp[tid*4],thp[tid*4+1]),
                                  fminf(thp[tid*4+2],thp[tid*4+3])) + DELTA;
            __syncthreads();
            #pragma unroll
            for (int lr=0; lr<4; ++lr) thr[lr] = thrS[R[lr]];
        }

        #pragma unroll 1
        for (int c=0; c<4; ++c){
            const int ch = (pass==0) ? c : (3-c);   // pass1 reversed; chunk 3 resident
            if (!(pass==1 && c==0)){
                const uint4* src = ((const uint4*)g_cbb) + ch*2048;
                #pragma unroll
                for (int j=tid; j<2048; j+=256){
                    uint32_t dst = Bu + (uint32_t)(j>>3)*144u + (uint32_t)(j&7)*16u;
                    CPASYNC16(dst, src + j);
                }
                if (tid<64)
                    CPASYNC16(CNu + tid*16u, (const uint4*)(g_cnorm + ch*256) + tid);
                asm volatile("cp.async.commit_group;" ::: "memory");
                asm volatile("cp.async.wait_group 0;" ::: "memory");
                __syncthreads();
            }

            #pragma unroll 1
            for (int it=0; it<4; ++it){
                int n0 = nq*64 + it*16;               // two n8-tiles: n0, n0+8
                uint32_t f0[8], f1[8];
                uint32_t a0 = lds_base + (uint32_t)n0*144u;
                uint32_t a1 = lds_base + (uint32_t)(n0+8)*144u;
                LDSM4(f0,   a0); LDSM4(f0+4, a0+64u);
                LDSM4(f1,   a1); LDSM4(f1+4, a1+64u);

                float acc[2][2][4];
                #pragma unroll
                for (int mt=0;mt<2;++mt)
                    #pragma unroll
                    for (int nt=0;nt<2;++nt)
                        { acc[mt][nt][0]=0;acc[mt][nt][1]=0;acc[mt][nt][2]=0;acc[mt][nt][3]=0; }
                #pragma unroll
                for (int ks=0; ks<4; ++ks){
                    #pragma unroll
                    for (int mt=0;mt<2;++mt){
                        HMMA(acc[mt][0], afr[mt][ks], f0[2*ks], f0[2*ks+1]);
                        HMMA(acc[mt][1], afr[mt][ks], f1[2*ks], f1[2*ks+1]);
                    }
                }

                float2 cnA = *(const float2*)&cns[n0 + 2*tg];
                float2 cnB = *(const float2*)&cns[n0 + 8 + 2*tg];
                float s[2][2][4];
                #pragma unroll
                for (int mt=0;mt<2;++mt)
                    #pragma unroll
                    for (int j=0;j<4;++j){
                        s[mt][0][j] = fmaf(-2.0f, acc[mt][0][j], (j&1)?cnA.y:cnA.x);
                        s[mt][1][j] = fmaf(-2.0f, acc[mt][1][j], (j&1)?cnB.y:cnB.x);
                    }
                float im[4];
                #pragma unroll
                for (int lr=0; lr<4; ++lr){
                    int mt = lr>>1, jb = (lr&1)*2;
                    im[lr] = fminf(fminf(s[mt][0][jb], s[mt][0][jb+1]),
                                   fminf(s[mt][1][jb], s[mt][1][jb+1]));
                }

                if (pass==0){
                    #pragma unroll
                    for (int lr=0; lr<4; ++lr) rm[lr] = fminf(rm[lr], im[lr]);
                } else {
                    bool hit = (im[0]<thr[0])|(im[1]<thr[1])|(im[2]<thr[2])|(im[3]<thr[3]);
                    if (__any_sync(0xffffffffu, hit)){
                        #pragma unroll
                        for (int mt=0;mt<2;++mt)
                            #pragma unroll
                            for (int nt=0;nt<2;++nt)
                                #pragma unroll
                                for (int j=0;j<4;++j){
                                    int lr = mt*2 + (j>>1);
                                    if (s[mt][nt][j] < thr[lr]){
                                        int k = ch*256 + n0 + 8*nt + 2*tg + (j&1);
                                        int pos = atomicAdd(wc, 1);
                                        if (pos < WL_CAP)
                                            wl[pos] = (uint16_t)((R[lr]<<10) | k);
                                    }
                                }
                    }
                }
            }
            __syncthreads();   // B consumed before next chunk overwrite
        }
    }

    // ======== staged exact rescore (R1 numerics): 128 items per round ========
    {
        int nwRaw = wc[0];
        if (nwRaw <= WL_CAP){
            #pragma unroll 1
            for (int base = 0; base < nwRaw; base += 128){
                int nit = nwRaw - base; if (nit > 128) nit = 128;
                #pragma unroll 1
                for (int c2 = tid; c2 < nit*16; c2 += 256){
                    int it2 = c2 >> 4, part = c2 & 15;
                    int k = wl[base+it2] & 1023;
                    uint4 v = __ldg(((const uint4*)cb) + k*16 + part);
                    float* dp = stg + it2*67 + part*4;
                    dp[0] = __uint_as_float(v.x);
                    dp[1] = __uint_as_float(v.y);
                    dp[2] = __uint_as_float(v.z);
                    dp[3] = __uint_as_float(v.w);
                }
                __syncthreads();
                if (tid < nit){
                    int item = wl[base+tid];
                    int row = item >> 10, k = item & 1023;
                    const float* cs2 = stg + tid*67;
                    float dot = 0.0f;
                    #pragma unroll
                    for (int d = 0; d < 64; ++d)
                        dot = fmaf(xs[d*64 + row], cs2[d], dot);
                    float sc = __fsub_rn(__fadd_rn(xns[row], __ldg(&g_cnorm[k])),
                                         __fmul_rn(2.0f, dot));
                    unsigned long long p = ((unsigned long long)f2o(sc)<<32) | (unsigned)k;
                    atomicMin(&brm[row], p);
                }
                __syncthreads();
            }
        } else {
            // deterministic full fallback (degenerate inputs only)
            int row = tid&63, q = tid>>6;
            float xnv = xns[row];
            #pragma unroll 1
            for (int k = q*256; k < q*256+256; ++k){
                const float4* cr = (const float4*)(cb + k*DIM);
                float dot = 0.0f;
                #pragma unroll
                for (int qq=0; qq<16; ++qq){
                    float4 cv = __ldg(cr+qq);
                    int dd = qq*4;
                    dot = fmaf(xs[dd*64+row],     cv.x, dot);
                    dot = fmaf(xs[(dd+1)*64+row], cv.y, dot);
                    dot = fmaf(xs[(dd+2)*64+row], cv.z, dot);
                    dot = fmaf(xs[(dd+3)*64+row], cv.w, dot);
                }
                float sc = __fsub_rn(__fadd_rn(xnv, __ldg(&g_cnorm[k])),
                                     __fmul_rn(2.0f, dot));
                unsigned long long p = ((unsigned long long)f2o(sc)<<32) | (unsigned)k;
                atomicMin(&brm[row], p);
            }
            __syncthreads();
        }
    }

    if (tid<64) sid[tid] = (int)(brm[tid] & 0x3FFull);
    __syncthreads();

    // ---- stage winner rows (coalesced) into stg: qs[row][d], stride 67 ----
    #pragma unroll
    for (int c2 = tid; c2 < 1024; c2 += 256){
        int row = c2 >> 4, part = c2 & 15;
        uint4 v = __ldg(((const uint4*)cb) + sid[row]*16 + part);
        float* dp = stg + row*67 + part*4;
        dp[0] = __uint_as_float(v.x);
        dp[1] = __uint_as_float(v.y);
        dp[2] = __uint_as_float(v.z);
        dp[3] = __uint_as_float(v.w);
    }
    __syncthreads();

    // ---- straight-through output + loss (R1 elementwise rounding) ----
    float lsum = 0.0f;
    {
        int w2 = tid&63, d0 = tid>>6;
        const float* qrow = stg + w2*67;
        float* ob = out + (size_t)b*DIM*HW + (size_t)h*64 + w2;
        #pragma unroll
        for (int i=0;i<16;i++){
            int d = d0*16+i;
            float q = qrow[d], xv = xs[d*64+w2];
            float df = __fsub_rn(q, xv);
            lsum = __fadd_rn(lsum, __fmul_rn(df, df));
            ob[(size_t)d*HW] = __fadd_rn(xv, df);
        }
    }
    lrd[tid] = lsum;
    __syncthreads();
    #pragma unroll
    for (int s2=128; s2>0; s2>>=1){
        if (tid<s2) lrd[tid] = __fadd_rn(lrd[tid], lrd[tid+s2]);
        __syncthreads();
    }
    if (tid==0) atomicAdd(loss_ptr, lrd[0] * (1.25f/(float)QELEMS));
}

extern "C" void kernel_launch(void* const* d_in, const int* in_sizes, int n_in,
                              void* d_out, int out_size) {
    const float* x  = (const float*)d_in[0];
    const float* cb = (const float*)d_in[1];
    float* out = (float*)d_out;
    float* loss_ptr = out + (out_size - 1);

    cudaFuncSetAttribute(vq_hmma_kernel, cudaFuncAttributeMaxDynamicSharedMemorySize, SMEM_BYTES);
    vq_prep<<<4, 256>>>(cb, loss_ptr);
    vq_hmma_kernel<<<1024, 256, SMEM_BYTES>>>(x, cb, out, loss_ptr);
}